// round 15
// baseline (speedup 1.0000x reference)
#include <cuda_runtime.h>
#include <cstdint>

#define CC 64
#define HWN 262144
#define NB 256
#define FINE 32768             // 2^15 fine bins per channel (lambda ~ 4)
#define WBIN (1.0f / (float)FINE)
#define TILEB 2048
#define NT (FINE / TILEB)      // 16 tiles per channel

// ---------------- scratch ----------------------------------------------------------
__device__ int            g_nI, g_nJ;
__device__ int            g_minJ[CC];    // float bits (values >= 0 -> int order == float order)
__device__ int            g_maxJ[CC];
__device__ int            g_histJ[CC * NB];
__device__ int            g_cntI[CC * FINE];     // counts -> (in place) tile-local offsets (8MB)
__device__ int            g_tbase[CC * NT];      // per-tile totals (scanned in k_loss)
__device__ double         g_loss;
__device__ unsigned int   g_done;

static __device__ __forceinline__ int fbin(float x) {
    int b = (int)(x * (float)FINE);
    return b < 0 ? 0 : (b > FINE - 1 ? FINE - 1 : b);
}

// ---------------- K0a (main): zero I counters + globals -------------------------------
__global__ void k_initI() {
    int i = blockIdx.x * blockDim.x + threadIdx.x;   // CC*FINE/4 threads
    ((int4*)g_cntI)[i] = make_int4(0, 0, 0, 0);
    if (i == 0) { g_nI = 0; g_loss = 0.0; g_done = 0u; }
}

// ---------------- K0b (aux): zero J-side state ----------------------------------------
__global__ void k_initJ() {
    int i = blockIdx.x * blockDim.x + threadIdx.x;   // CC*NB threads
    g_histJ[i] = 0;
    if (i < CC) { g_minJ[i] = 0x7F800000; g_maxJ[i] = 0; }
    if (i == 0) g_nJ = 0;
}

// ---------------- K1 (aux): minmax(J) + nJ (pure BW pass) -----------------------------
__global__ void k_passJmm(const float4* __restrict__ J, const int4* __restrict__ mJ4) {
    int c = blockIdx.y;
    int i = blockIdx.x * blockDim.x + threadIdx.x;     // HWN/8 per channel
    int base = c * (HWN / 4) + i * 2;
    float4 j0 = J[base], j1 = J[base + 1];
    int4  mj0 = mJ4[i * 2], mj1 = mJ4[i * 2 + 1];

    float mn = 1e30f, mx = -1e30f;
    if (mj0.x) { mn = fminf(mn, j0.x); mx = fmaxf(mx, j0.x); }
    if (mj0.y) { mn = fminf(mn, j0.y); mx = fmaxf(mx, j0.y); }
    if (mj0.z) { mn = fminf(mn, j0.z); mx = fmaxf(mx, j0.z); }
    if (mj0.w) { mn = fminf(mn, j0.w); mx = fmaxf(mx, j0.w); }
    if (mj1.x) { mn = fminf(mn, j1.x); mx = fmaxf(mx, j1.x); }
    if (mj1.y) { mn = fminf(mn, j1.y); mx = fmaxf(mx, j1.y); }
    if (mj1.z) { mn = fminf(mn, j1.z); mx = fmaxf(mx, j1.z); }
    if (mj1.w) { mn = fminf(mn, j1.w); mx = fmaxf(mx, j1.w); }

    if (c == 0) {
        int sJ = mj0.x + mj0.y + mj0.z + mj0.w + mj1.x + mj1.y + mj1.z + mj1.w;
        for (int o = 16; o; o >>= 1) sJ += __shfl_down_sync(0xFFFFFFFFu, sJ, o);
        if ((threadIdx.x & 31) == 0) atomicAdd(&g_nJ, sJ);
    }
    for (int o = 16; o; o >>= 1) {
        mn = fminf(mn, __shfl_down_sync(0xFFFFFFFFu, mn, o));
        mx = fmaxf(mx, __shfl_down_sync(0xFFFFFFFFu, mx, o));
    }
    __shared__ float smn[8], smx[8];
    int t = threadIdx.x;
    if ((t & 31) == 0) { smn[t >> 5] = mn; smx[t >> 5] = mx; }
    __syncthreads();
    if (t < 8) {
        mn = smn[t]; mx = smx[t];
        for (int o = 4; o; o >>= 1) {
            mn = fminf(mn, __shfl_down_sync(0xFFu, mn, o));
            mx = fmaxf(mx, __shfl_down_sync(0xFFu, mx, o));
        }
        if (t == 0) {
            if (mn < 1e30f)  atomicMin(&g_minJ[c], __float_as_int(mn));
            if (mx > -1e30f) atomicMax(&g_maxJ[c], __float_as_int(mx));
        }
    }
}

// ---------------- K2 (aux): exact coarse histogram of J (4-replica shared) ------------
__global__ void k_histJ(const float4* __restrict__ J, const int4* __restrict__ mJ4) {
    __shared__ int sh[4 * NB];
    int c = blockIdx.y;
    int t = threadIdx.x;
    #pragma unroll
    for (int k = 0; k < 4; k++) sh[k * NB + t] = 0;
    __syncthreads();
    float minf = __int_as_float(g_minJ[c]);
    float maxf = __int_as_float(g_maxJ[c]);
    float step = (maxf - minf) * (1.0f / NB);
    float sden = fmaxf(step, 1e-12f);
    int i = blockIdx.x * blockDim.x + t;
    int base = c * (HWN / 4) + i * 2;
    float4 v0 = J[base], v1 = J[base + 1];
    int4  m0 = mJ4[i * 2], m1 = mJ4[i * 2 + 1];
    int* h = sh + (t & 3) * NB;
    #define HADD(mm, vv) if (mm) { int b = (int)floorf((vv - minf) / sden); b = max(0, min(NB - 1, b)); atomicAdd(&h[b], 1); }
    HADD(m0.x, v0.x) HADD(m0.y, v0.y) HADD(m0.z, v0.z) HADD(m0.w, v0.w)
    HADD(m1.x, v1.x) HADD(m1.y, v1.y) HADD(m1.z, v1.z) HADD(m1.w, v1.w)
    #undef HADD
    __syncthreads();
    int s = sh[t] + sh[NB + t] + sh[2 * NB + t] + sh[3 * NB + t];
    if (s) atomicAdd(&g_histJ[c * NB + t], s);
}

// ---------------- K3 (main): fine-count I + nI ----------------------------------------
__global__ void k_passI(const float4* __restrict__ I, const int4* __restrict__ mI4) {
    int c = blockIdx.y;
    int i = blockIdx.x * blockDim.x + threadIdx.x;
    int base = c * (HWN / 4) + i * 2;
    float4 i0 = I[base], i1 = I[base + 1];
    int4  mi0 = mI4[i * 2], mi1 = mI4[i * 2 + 1];

    int* cnt = g_cntI + c * FINE;
    #define FC(mm, vv) if (mm) atomicAdd(&cnt[fbin(vv)], 1);
    FC(mi0.x, i0.x) FC(mi0.y, i0.y) FC(mi0.z, i0.z) FC(mi0.w, i0.w)
    FC(mi1.x, i1.x) FC(mi1.y, i1.y) FC(mi1.z, i1.z) FC(mi1.w, i1.w)
    #undef FC

    if (c == 0) {
        int sI = mi0.x + mi0.y + mi0.z + mi0.w + mi1.x + mi1.y + mi1.z + mi1.w;
        for (int o = 16; o; o >>= 1) sI += __shfl_down_sync(0xFFFFFFFFu, sI, o);
        if ((threadIdx.x & 31) == 0) atomicAdd(&g_nI, sI);
    }
}

// ---------------- K4 (main): per-tile in-place exclusive scan of I counts -------------
__global__ void k_mid() {
    int c = blockIdx.y, tile = blockIdx.x, t = threadIdx.x;   // 256 threads, 2048 bins
    int base = c * FINE + tile * TILEB + t * 8;
    int4 a = *(const int4*)&g_cntI[base];
    int4 b4 = *(const int4*)&g_cntI[base + 4];
    int v[8] = {a.x, a.y, a.z, a.w, b4.x, b4.y, b4.z, b4.w};
    int loc[8];
    int run = 0;
    #pragma unroll
    for (int k = 0; k < 8; k++) { loc[k] = run; run += v[k]; }
    int lane = t & 31, wid = t >> 5;
    int x = run;
    for (int o = 1; o < 32; o <<= 1) {
        int u = __shfl_up_sync(0xFFFFFFFFu, x, o);
        if (lane >= o) x += u;
    }
    __shared__ int wsum[8];
    if (lane == 31) wsum[wid] = x;
    __syncthreads();
    if (t < 8) {
        int y = wsum[t];
        for (int o = 1; o < 8; o <<= 1) {
            int u = __shfl_up_sync(0xFFu, y, o);
            if (t >= o) y += u;
        }
        wsum[t] = y;
    }
    __syncthreads();
    int ex = x - run + (wid ? wsum[wid - 1] : 0);
    *(int4*)&g_cntI[base]     = make_int4(ex + loc[0], ex + loc[1], ex + loc[2], ex + loc[3]);
    *(int4*)&g_cntI[base + 4] = make_int4(ex + loc[4], ex + loc[5], ex + loc[6], ex + loc[7]);
    if (t == 255) g_tbase[c * NT + tile] = ex + run;
}

// ---------------- K5: closed-form per-bin loss ----------------------------------------
__global__ void k_loss(float* __restrict__ out) {
    int c = blockIdx.y, tile = blockIdx.x, t = threadIdx.x;   // 256 threads, 8 bins each
    __shared__ float scum[NB], shis[NB], sh[NB];
    __shared__ int stb[NT + 1];
    if (t < NT) {
        int tot = g_tbase[c * NT + t];
        int incl = tot;
        for (int o = 1; o < NT; o <<= 1) {
            int u = __shfl_up_sync(0xFFFFu, incl, o);
            if (t >= o) incl += u;
        }
        stb[t] = incl - tot;
        if (t == NT - 1) stb[NT] = incl;                 // channel total
    }
    float scale = (float)g_nI / (float)g_nJ;
    float h = (float)g_histJ[c * NB + t] * scale;
    shis[t] = h;
    sh[t] = h;
    __syncthreads();
    for (int o = 1; o < NB; o <<= 1) {
        float add = (t >= o) ? sh[t - o] : 0.0f;
        __syncthreads();
        sh[t] += add;
        __syncthreads();
    }
    scum[t] = sh[t];
    __syncthreads();

    float minf = __int_as_float(g_minJ[c]);
    float maxf = __int_as_float(g_maxJ[c]);
    float step = (maxf - minf) * (1.0f / NB);

    int base = c * FINE + tile * TILEB + t * 8;
    int4 a = *(const int4*)&g_cntI[base];
    int4 bq = *(const int4*)&g_cntI[base + 4];
    int o9[9] = {a.x, a.y, a.z, a.w, bq.x, bq.y, bq.z, bq.w, 0};
    int tb = stb[tile];
    if (t < 255) o9[8] = g_cntI[base + 8];
    int e_thread_last = (t < 255) ? (tb + o9[8]) : stb[tile + 1];

    int bi = -1;
    float cum_bi = 0.0f, lo = 0.0f, invh = 0.0f, fb = 0.0f;
    float acc = 0.0f;

    for (int k = 0; k < 8; k++) {
        int s = tb + o9[k];
        int e = (k < 7) ? (tb + o9[k + 1]) : e_thread_last;
        if (e <= s) continue;
        float xb = ((float)(tile * TILEB + t * 8 + k) + 0.5f) * WBIN;  // bin center
        int r0 = s + 1;
        while (r0 <= e) {
            if (bi < 0) {
                float r = (float)r0;
                int pos = 0;
                #pragma unroll
                for (int st = 128; st > 0; st >>= 1) {
                    int np = pos + st;
                    if (np <= NB && scum[np - 1] < r) pos = np;
                }
                bi = pos > NB - 1 ? NB - 1 : pos;
                cum_bi = scum[bi]; float hb = shis[bi];
                lo = cum_bi - hb; invh = 1.0f / fmaxf(hb, 1e-12f);
                fb = minf + (float)bi * step;
            } else {
                while ((float)r0 > cum_bi && bi < NB - 1) {
                    bi++;
                    cum_bi = scum[bi]; float hb = shis[bi];
                    lo = cum_bi - hb; invh = 1.0f / fmaxf(hb, 1e-12f);
                    fb = minf + (float)bi * step;
                }
            }
            if (bi == NB - 1 && (float)r0 > cum_bi) {    // clamp region: ratio = 1
                float d = xb - (fb + step);
                float fn = (float)(e - r0 + 1);
                acc = fmaf(fn * d, d, acc);
                r0 = e + 1;
                continue;
            }
            int rend = e;
            if ((float)e > cum_bi) {
                int rb = (int)floorf(cum_bi);
                rend = rb < e ? rb : e;
            }
            float a0 = xb - fb - ((float)r0 - lo) * invh * step;
            float q  = -invh * step;
            float fn = (float)(rend - r0 + 1);
            float s1 = 0.5f * fn * (fn - 1.0f);
            float s2 = (fn - 1.0f) * fn * (2.0f * fn - 1.0f) * (1.0f / 6.0f);
            acc += fn * a0 * a0 + 2.0f * a0 * q * s1 + q * q * s2;
            r0 = rend + 1;
        }
    }

    double dacc = (double)acc;
    for (int o = 16; o; o >>= 1) dacc += __shfl_down_sync(0xFFFFFFFFu, dacc, o);
    __shared__ double sacc[8];
    if ((t & 31) == 0) sacc[t >> 5] = dacc;
    __syncthreads();
    if (t < 8) {
        double v = sacc[t];
        for (int o = 4; o; o >>= 1) v += __shfl_down_sync(0xFFu, v, o);
        if (t == 0) {
            atomicAdd(&g_loss, v);
            __threadfence();
            unsigned int ticket = atomicAdd(&g_done, 1u);
            if (ticket == (unsigned)(CC * NT) - 1) {
                double tot = atomicAdd(&g_loss, 0.0);
                out[0] = (float)(tot * (100.0 / ((double)CC * (double)HWN)));
            }
        }
    }
}

extern "C" void kernel_launch(void* const* d_in, const int* in_sizes, int n_in,
                              void* d_out, int out_size) {
    const float* I = (const float*)d_in[0];
    const float* J = (const float*)d_in[1];
    const int*  mI = (const int*)d_in[2];
    const int*  mJ = (const int*)d_in[3];
    float* out = (float*)d_out;

    static cudaStream_t s_aux = nullptr;
    static cudaEvent_t  ev_fork = nullptr, ev_join = nullptr;
    if (!s_aux) {
        cudaStreamCreateWithFlags(&s_aux, cudaStreamNonBlocking);
        cudaEventCreateWithFlags(&ev_fork, cudaEventDisableTiming);
        cudaEventCreateWithFlags(&ev_join, cudaEventDisableTiming);
    }

    dim3 g8((HWN / 8) / 256, CC);   // 128 x 64, 8 elems/thread
    dim3 gs(NT, CC);                // 16 x 64

    // ---- fork aux from capture origin (required for graph capture) ----
    cudaEventRecord(ev_fork, 0);
    cudaStreamWaitEvent(s_aux, ev_fork, 0);

    // ---- aux stream: ENTIRE J pipeline (DRAM + shared-atomic bound) ----
    k_initJ<<<(CC * NB) / 256, 256, 0, s_aux>>>();
    k_passJmm<<<g8, 256, 0, s_aux>>>((const float4*)J, (const int4*)mJ);
    k_histJ<<<g8, 256, 0, s_aux>>>((const float4*)J, (const int4*)mJ);
    cudaEventRecord(ev_join, s_aux);

    // ---- main stream: ENTIRE I pipeline (L2-atomic bound) ----
    k_initI<<<(CC * FINE / 4) / 1024, 1024>>>();
    k_passI<<<g8, 256>>>((const float4*)I, (const int4*)mI);
    k_mid<<<gs, 256>>>();

    // ---- join, then loss ----
    cudaStreamWaitEvent(0, ev_join, 0);
    k_loss<<<gs, 256>>>(out);
}

// round 16
// speedup vs baseline: 1.3236x; 1.3236x over previous
#include <cuda_runtime.h>
#include <cstdint>

#define CC 64
#define HWN 262144
#define NB 256
#define FINE 32768             // 2^15 fine bins per channel
#define WBIN (1.0f / (float)FINE)
#define TILEB 2048
#define NT (FINE / TILEB)      // 16 tiles per channel
#define SMEM_HIST (FINE * 4)   // 128KB dynamic smem

// ---------------- scratch ----------------------------------------------------------
__device__ int           g_minJ[CC];     // float bits (values >= 0 -> int order == float order)
__device__ int           g_maxJ[CC];
__device__ int           g_histJ[CC * NB];
__device__ int           g_cntA[CC * FINE];     // half-0 counts -> (in place) tile-local offsets
__device__ int           g_cntB[CC * FINE];     // half-1 counts
__device__ int           g_tbase[CC * NT];
__device__ double        g_loss;
__device__ unsigned int  g_done;

static __device__ __forceinline__ int fbin(float x) {
    int b = (int)(x * (float)FINE);
    return b < 0 ? 0 : (b > FINE - 1 ? FINE - 1 : b);
}

// ---------------- K0 (aux): zero J-side state -----------------------------------------
__global__ void k_initJ() {
    int i = blockIdx.x * blockDim.x + threadIdx.x;   // CC*NB threads
    g_histJ[i] = 0;
    if (i < CC) { g_minJ[i] = 0x7F800000; g_maxJ[i] = 0; }
}

// ---------------- K1 (aux): minmax(J) (pure BW pass) ----------------------------------
__global__ void k_passJmm(const float4* __restrict__ J, const int4* __restrict__ mJ4) {
    int c = blockIdx.y;
    int i = blockIdx.x * blockDim.x + threadIdx.x;     // HWN/8 per channel
    int base = c * (HWN / 4) + i * 2;
    float4 j0 = J[base], j1 = J[base + 1];
    int4  mj0 = mJ4[i * 2], mj1 = mJ4[i * 2 + 1];

    float mn = 1e30f, mx = -1e30f;
    if (mj0.x) { mn = fminf(mn, j0.x); mx = fmaxf(mx, j0.x); }
    if (mj0.y) { mn = fminf(mn, j0.y); mx = fmaxf(mx, j0.y); }
    if (mj0.z) { mn = fminf(mn, j0.z); mx = fmaxf(mx, j0.z); }
    if (mj0.w) { mn = fminf(mn, j0.w); mx = fmaxf(mx, j0.w); }
    if (mj1.x) { mn = fminf(mn, j1.x); mx = fmaxf(mx, j1.x); }
    if (mj1.y) { mn = fminf(mn, j1.y); mx = fmaxf(mx, j1.y); }
    if (mj1.z) { mn = fminf(mn, j1.z); mx = fmaxf(mx, j1.z); }
    if (mj1.w) { mn = fminf(mn, j1.w); mx = fmaxf(mx, j1.w); }

    for (int o = 16; o; o >>= 1) {
        mn = fminf(mn, __shfl_down_sync(0xFFFFFFFFu, mn, o));
        mx = fmaxf(mx, __shfl_down_sync(0xFFFFFFFFu, mx, o));
    }
    __shared__ float smn[8], smx[8];
    int t = threadIdx.x;
    if ((t & 31) == 0) { smn[t >> 5] = mn; smx[t >> 5] = mx; }
    __syncthreads();
    if (t < 8) {
        mn = smn[t]; mx = smx[t];
        for (int o = 4; o; o >>= 1) {
            mn = fminf(mn, __shfl_down_sync(0xFFu, mn, o));
            mx = fmaxf(mx, __shfl_down_sync(0xFFu, mx, o));
        }
        if (t == 0) {
            if (mn < 1e30f)  atomicMin(&g_minJ[c], __float_as_int(mn));
            if (mx > -1e30f) atomicMax(&g_maxJ[c], __float_as_int(mx));
        }
    }
}

// ---------------- K2 (aux): exact coarse histogram of J (4-replica shared) ------------
__global__ void k_histJ(const float4* __restrict__ J, const int4* __restrict__ mJ4) {
    __shared__ int sh[4 * NB];
    int c = blockIdx.y;
    int t = threadIdx.x;
    #pragma unroll
    for (int k = 0; k < 4; k++) sh[k * NB + t] = 0;
    __syncthreads();
    float minf = __int_as_float(g_minJ[c]);
    float maxf = __int_as_float(g_maxJ[c]);
    float step = (maxf - minf) * (1.0f / NB);
    float sden = fmaxf(step, 1e-12f);
    int i = blockIdx.x * blockDim.x + t;
    int base = c * (HWN / 4) + i * 2;
    float4 v0 = J[base], v1 = J[base + 1];
    int4  m0 = mJ4[i * 2], m1 = mJ4[i * 2 + 1];
    int* h = sh + (t & 3) * NB;
    #define HADD(mm, vv) if (mm) { int b = (int)floorf((vv - minf) / sden); b = max(0, min(NB - 1, b)); atomicAdd(&h[b], 1); }
    HADD(m0.x, v0.x) HADD(m0.y, v0.y) HADD(m0.z, v0.z) HADD(m0.w, v0.w)
    HADD(m1.x, v1.x) HADD(m1.y, v1.y) HADD(m1.z, v1.z) HADD(m1.w, v1.w)
    #undef HADD
    __syncthreads();
    int s = sh[t] + sh[NB + t] + sh[2 * NB + t] + sh[3 * NB + t];
    if (s) atomicAdd(&g_histJ[c * NB + t], s);
}

// ---------------- K3 (main): fine-count I via SM-private 128KB smem histogram ---------
__global__ void __launch_bounds__(1024) k_cntI(const float4* __restrict__ I,
                                               const int4* __restrict__ mI4) {
    extern __shared__ int shist[];                 // FINE ints = 128KB
    int c = blockIdx.x >> 1;                       // 2 CTAs per channel
    int half = blockIdx.x & 1;
    int t = threadIdx.x;
    #pragma unroll
    for (int k = 0; k < FINE / 4 / 1024; k++)      // 8 x int4 per thread
        ((int4*)shist)[k * 1024 + t] = make_int4(0, 0, 0, 0);
    __syncthreads();

    int base4 = c * (HWN / 4) + half * (HWN / 8);  // float4 index
    int mbase4 = half * (HWN / 8);
    #pragma unroll 4
    for (int it = 0; it < (HWN / 8) / 1024; it++) {  // 32 iterations
        int idx = it * 1024 + t;
        float4 v = I[base4 + idx];
        int4  m = mI4[mbase4 + idx];
        if (m.x) atomicAdd(&shist[fbin(v.x)], 1);
        if (m.y) atomicAdd(&shist[fbin(v.y)], 1);
        if (m.z) atomicAdd(&shist[fbin(v.z)], 1);
        if (m.w) atomicAdd(&shist[fbin(v.w)], 1);
    }
    __syncthreads();

    int* dst = (half ? g_cntB : g_cntA) + c * FINE;
    #pragma unroll
    for (int k = 0; k < FINE / 4 / 1024; k++)
        ((int4*)dst)[k * 1024 + t] = ((const int4*)shist)[k * 1024 + t];
}

// ---------------- K4 (main): scan(A+B) in place into A; zero loss state ---------------
__global__ void k_mid() {
    int c = blockIdx.y, tile = blockIdx.x, t = threadIdx.x;   // 256 threads, 2048 bins
    if (blockIdx.x == 0 && blockIdx.y == 0 && t == 0) { g_loss = 0.0; g_done = 0u; }
    int base = c * FINE + tile * TILEB + t * 8;
    int4 a0 = *(const int4*)&g_cntA[base];
    int4 a1 = *(const int4*)&g_cntA[base + 4];
    int4 b0 = *(const int4*)&g_cntB[base];
    int4 b1 = *(const int4*)&g_cntB[base + 4];
    int v[8] = {a0.x + b0.x, a0.y + b0.y, a0.z + b0.z, a0.w + b0.w,
                a1.x + b1.x, a1.y + b1.y, a1.z + b1.z, a1.w + b1.w};
    int loc[8];
    int run = 0;
    #pragma unroll
    for (int k = 0; k < 8; k++) { loc[k] = run; run += v[k]; }
    int lane = t & 31, wid = t >> 5;
    int x = run;
    for (int o = 1; o < 32; o <<= 1) {
        int u = __shfl_up_sync(0xFFFFFFFFu, x, o);
        if (lane >= o) x += u;
    }
    __shared__ int wsum[8];
    if (lane == 31) wsum[wid] = x;
    __syncthreads();
    if (t < 8) {
        int y = wsum[t];
        for (int o = 1; o < 8; o <<= 1) {
            int u = __shfl_up_sync(0xFFu, y, o);
            if (t >= o) y += u;
        }
        wsum[t] = y;
    }
    __syncthreads();
    int ex = x - run + (wid ? wsum[wid - 1] : 0);
    *(int4*)&g_cntA[base]     = make_int4(ex + loc[0], ex + loc[1], ex + loc[2], ex + loc[3]);
    *(int4*)&g_cntA[base + 4] = make_int4(ex + loc[4], ex + loc[5], ex + loc[6], ex + loc[7]);
    if (t == 255) g_tbase[c * NT + tile] = ex + run;
}

// ---------------- K5: closed-form per-bin loss ----------------------------------------
__global__ void k_loss(float* __restrict__ out) {
    int c = blockIdx.y, tile = blockIdx.x, t = threadIdx.x;   // 256 threads, 8 bins each
    __shared__ float scum[NB], shis[NB];
    __shared__ int sicum[NB];
    __shared__ int stb[NT + 1];
    int hraw = g_histJ[c * NB + t];
    if (t < NT) {
        int tot = g_tbase[c * NT + t];
        int incl = tot;
        for (int o = 1; o < NT; o <<= 1) {
            int u = __shfl_up_sync(0xFFFFu, incl, o);
            if (t >= o) incl += u;
        }
        stb[t] = incl - tot;
        if (t == NT - 1) stb[NT] = incl;                 // channel total = nI
    }
    sicum[t] = hraw;
    __syncthreads();
    for (int o = 1; o < NB; o <<= 1) {
        int add = (t >= o) ? sicum[t - o] : 0;
        __syncthreads();
        sicum[t] += add;
        __syncthreads();
    }
    float nI = (float)stb[NT];
    float nJ = (float)sicum[NB - 1];
    float scale = nI / nJ;
    scum[t] = (float)sicum[t] * scale;
    shis[t] = (float)hraw * scale;
    __syncthreads();

    float minf = __int_as_float(g_minJ[c]);
    float maxf = __int_as_float(g_maxJ[c]);
    float step = (maxf - minf) * (1.0f / NB);

    int base = c * FINE + tile * TILEB + t * 8;
    int4 a = *(const int4*)&g_cntA[base];
    int4 bq = *(const int4*)&g_cntA[base + 4];
    int o9[9] = {a.x, a.y, a.z, a.w, bq.x, bq.y, bq.z, bq.w, 0};
    int tb = stb[tile];
    if (t < 255) o9[8] = g_cntA[base + 8];
    int e_thread_last = (t < 255) ? (tb + o9[8]) : stb[tile + 1];

    int bi = -1;
    float cum_bi = 0.0f, lo = 0.0f, invh = 0.0f, fb = 0.0f;
    float acc = 0.0f;

    for (int k = 0; k < 8; k++) {
        int s = tb + o9[k];
        int e = (k < 7) ? (tb + o9[k + 1]) : e_thread_last;
        if (e <= s) continue;
        float xb = ((float)(tile * TILEB + t * 8 + k) + 0.5f) * WBIN;  // bin center
        int r0 = s + 1;
        while (r0 <= e) {
            if (bi < 0) {
                float r = (float)r0;
                int pos = 0;
                #pragma unroll
                for (int st = 128; st > 0; st >>= 1) {
                    int np = pos + st;
                    if (np <= NB && scum[np - 1] < r) pos = np;
                }
                bi = pos > NB - 1 ? NB - 1 : pos;
                cum_bi = scum[bi]; float hb = shis[bi];
                lo = cum_bi - hb; invh = 1.0f / fmaxf(hb, 1e-12f);
                fb = minf + (float)bi * step;
            } else {
                while ((float)r0 > cum_bi && bi < NB - 1) {
                    bi++;
                    cum_bi = scum[bi]; float hb = shis[bi];
                    lo = cum_bi - hb; invh = 1.0f / fmaxf(hb, 1e-12f);
                    fb = minf + (float)bi * step;
                }
            }
            if (bi == NB - 1 && (float)r0 > cum_bi) {    // clamp region: ratio = 1
                float d = xb - (fb + step);
                float fn = (float)(e - r0 + 1);
                acc = fmaf(fn * d, d, acc);
                r0 = e + 1;
                continue;
            }
            int rend = e;
            if ((float)e > cum_bi) {
                int rb = (int)floorf(cum_bi);
                rend = rb < e ? rb : e;
            }
            float a0 = xb - fb - ((float)r0 - lo) * invh * step;
            float q  = -invh * step;
            float fn = (float)(rend - r0 + 1);
            float s1 = 0.5f * fn * (fn - 1.0f);
            float s2 = (fn - 1.0f) * fn * (2.0f * fn - 1.0f) * (1.0f / 6.0f);
            acc += fn * a0 * a0 + 2.0f * a0 * q * s1 + q * q * s2;
            r0 = rend + 1;
        }
    }

    double dacc = (double)acc;
    for (int o = 16; o; o >>= 1) dacc += __shfl_down_sync(0xFFFFFFFFu, dacc, o);
    __shared__ double sacc[8];
    if ((t & 31) == 0) sacc[t >> 5] = dacc;
    __syncthreads();
    if (t < 8) {
        double v = sacc[t];
        for (int o = 4; o; o >>= 1) v += __shfl_down_sync(0xFFu, v, o);
        if (t == 0) {
            atomicAdd(&g_loss, v);
            __threadfence();
            unsigned int ticket = atomicAdd(&g_done, 1u);
            if (ticket == (unsigned)(CC * NT) - 1) {
                double tot = atomicAdd(&g_loss, 0.0);
                out[0] = (float)(tot * (100.0 / ((double)CC * (double)HWN)));
            }
        }
    }
}

extern "C" void kernel_launch(void* const* d_in, const int* in_sizes, int n_in,
                              void* d_out, int out_size) {
    const float* I = (const float*)d_in[0];
    const float* J = (const float*)d_in[1];
    const int*  mI = (const int*)d_in[2];
    const int*  mJ = (const int*)d_in[3];
    float* out = (float*)d_out;

    static cudaStream_t s_aux = nullptr;
    static cudaEvent_t  ev_fork = nullptr, ev_join = nullptr;
    if (!s_aux) {
        cudaStreamCreateWithFlags(&s_aux, cudaStreamNonBlocking);
        cudaEventCreateWithFlags(&ev_fork, cudaEventDisableTiming);
        cudaEventCreateWithFlags(&ev_join, cudaEventDisableTiming);
        cudaFuncSetAttribute(k_cntI, cudaFuncAttributeMaxDynamicSharedMemorySize, SMEM_HIST);
    }

    dim3 g8((HWN / 8) / 256, CC);   // 128 x 64, 8 elems/thread
    dim3 gs(NT, CC);                // 16 x 64

    // ---- fork aux from capture origin ----
    cudaEventRecord(ev_fork, 0);
    cudaStreamWaitEvent(s_aux, ev_fork, 0);

    // ---- aux stream: J pipeline (DRAM + shared-atomic bound) ----
    k_initJ<<<(CC * NB) / 256, 256, 0, s_aux>>>();
    k_passJmm<<<g8, 256, 0, s_aux>>>((const float4*)J, (const int4*)mJ);
    k_histJ<<<g8, 256, 0, s_aux>>>((const float4*)J, (const int4*)mJ);
    cudaEventRecord(ev_join, s_aux);

    // ---- main stream: I pipeline (smem-hist, no global atomics) ----
    k_cntI<<<2 * CC, 1024, SMEM_HIST>>>((const float4*)I, (const int4*)mI);
    k_mid<<<gs, 256>>>();

    // ---- join, then loss ----
    cudaStreamWaitEvent(0, ev_join, 0);
    k_loss<<<gs, 256>>>(out);
}

// round 17
// speedup vs baseline: 1.4961x; 1.1303x over previous
#include <cuda_runtime.h>
#include <cstdint>

#define CC 64
#define HWN 262144
#define NB 256
#define IFINE 16384            // I fine bins (64KB smem)
#define JFINE 32768            // J fine bins (128KB smem)
#define IWBIN (1.0f / (float)IFINE)
#define JWBIN (1.0f / (float)JFINE)
#define NT 16                  // tiles per channel
#define ITILE (IFINE / NT)     // 1024 I bins per tile
#define JTILE (JFINE / NT)     // 2048 J bins per tile
#define SMEM_HIST ((IFINE + JFINE) * 4)   // 192KB dynamic smem

// ---------------- scratch ----------------------------------------------------------
__device__ int           g_minJ[CC];     // float bits (values >= 0 -> int order == float order)
__device__ int           g_maxJ[CC];
__device__ int           g_histJ[CC * NB];
__device__ int           g_cntA[CC * IFINE];    // I half-0 counts -> (in place) tile-local offsets
__device__ int           g_cntB[CC * IFINE];    // I half-1 counts
__device__ int           g_cntJA[CC * JFINE];   // J half-0 fine counts
__device__ int           g_cntJB[CC * JFINE];   // J half-1 fine counts
__device__ int           g_tbase[CC * NT];
__device__ double        g_loss;
__device__ unsigned int  g_done;

static __device__ __forceinline__ int fbinI(float x) {
    int b = (int)(x * (float)IFINE);
    return b < 0 ? 0 : (b > IFINE - 1 ? IFINE - 1 : b);
}
static __device__ __forceinline__ int fbinJ(float x) {
    int b = (int)(x * (float)JFINE);
    return b < 0 ? 0 : (b > JFINE - 1 ? JFINE - 1 : b);
}

// ---------------- K0: init ------------------------------------------------------------
__global__ void k_init() {
    int i = blockIdx.x * blockDim.x + threadIdx.x;   // CC*NB threads
    g_histJ[i] = 0;
    if (i < CC) { g_minJ[i] = 0x7F800000; g_maxJ[i] = 0; }
    if (i == 0) { g_loss = 0.0; g_done = 0u; }
}

// ---------------- K1: fused fine hist of I and J + exact minmax(J) --------------------
__global__ void __launch_bounds__(1024) k_hist(const float4* __restrict__ I,
                                               const float4* __restrict__ J,
                                               const int4* __restrict__ mI4,
                                               const int4* __restrict__ mJ4) {
    extern __shared__ int sh[];                    // [0,IFINE)=I hist, [IFINE,IFINE+JFINE)=J hist
    int c = blockIdx.x >> 1;                       // 2 CTAs per channel
    int half = blockIdx.x & 1;
    int t = threadIdx.x;
    #pragma unroll
    for (int k = 0; k < (IFINE + JFINE) / 4 / 1024; k++)   // 12 int4 per thread
        ((int4*)sh)[k * 1024 + t] = make_int4(0, 0, 0, 0);
    __syncthreads();

    int base4 = c * (HWN / 4) + half * (HWN / 8);
    int mbase4 = half * (HWN / 8);
    int* shJ = sh + IFINE;
    float mn = 1e30f, mx = -1e30f;
    #pragma unroll 2
    for (int it = 0; it < (HWN / 8) / 1024; it++) {        // 32 iterations
        int idx = it * 1024 + t;
        float4 vi = I[base4 + idx];
        int4  mi = mI4[mbase4 + idx];
        float4 vj = J[base4 + idx];
        int4  mj = mJ4[mbase4 + idx];
        if (mi.x) atomicAdd(&sh[fbinI(vi.x)], 1);
        if (mi.y) atomicAdd(&sh[fbinI(vi.y)], 1);
        if (mi.z) atomicAdd(&sh[fbinI(vi.z)], 1);
        if (mi.w) atomicAdd(&sh[fbinI(vi.w)], 1);
        if (mj.x) { atomicAdd(&shJ[fbinJ(vj.x)], 1); mn = fminf(mn, vj.x); mx = fmaxf(mx, vj.x); }
        if (mj.y) { atomicAdd(&shJ[fbinJ(vj.y)], 1); mn = fminf(mn, vj.y); mx = fmaxf(mx, vj.y); }
        if (mj.z) { atomicAdd(&shJ[fbinJ(vj.z)], 1); mn = fminf(mn, vj.z); mx = fmaxf(mx, vj.z); }
        if (mj.w) { atomicAdd(&shJ[fbinJ(vj.w)], 1); mn = fminf(mn, vj.w); mx = fmaxf(mx, vj.w); }
    }

    // exact minmax(J) block reduction
    for (int o = 16; o; o >>= 1) {
        mn = fminf(mn, __shfl_down_sync(0xFFFFFFFFu, mn, o));
        mx = fmaxf(mx, __shfl_down_sync(0xFFFFFFFFu, mx, o));
    }
    __shared__ float smn[32], smx[32];
    if ((t & 31) == 0) { smn[t >> 5] = mn; smx[t >> 5] = mx; }
    __syncthreads();
    if (t < 32) {
        mn = smn[t]; mx = smx[t];
        for (int o = 16; o; o >>= 1) {
            mn = fminf(mn, __shfl_down_sync(0xFFFFFFFFu, mn, o));
            mx = fmaxf(mx, __shfl_down_sync(0xFFFFFFFFu, mx, o));
        }
        if (t == 0) {
            if (mn < 1e30f)  atomicMin(&g_minJ[c], __float_as_int(mn));
            if (mx > -1e30f) atomicMax(&g_maxJ[c], __float_as_int(mx));
        }
    }
    __syncthreads();

    // flush fine histograms (coalesced int4 stores)
    int* dstI = (half ? g_cntB : g_cntA) + c * IFINE;
    #pragma unroll
    for (int k = 0; k < IFINE / 4 / 1024; k++)     // 4 int4
        ((int4*)dstI)[k * 1024 + t] = ((const int4*)sh)[k * 1024 + t];
    int* dstJ = (half ? g_cntJB : g_cntJA) + c * JFINE;
    #pragma unroll
    for (int k = 0; k < JFINE / 4 / 1024; k++)     // 8 int4
        ((int4*)dstJ)[k * 1024 + t] = ((const int4*)(sh + IFINE))[k * 1024 + t];
}

// ---------------- K2: scan I counts + fold J fine -> coarse ---------------------------
__global__ void k_mid() {
    int c = blockIdx.y, tile = blockIdx.x, t = threadIdx.x;   // 256 threads
    __shared__ int shh[2 * NB];
    shh[t] = 0; shh[t + NB] = 0;
    __syncthreads();

    // --- J fold: 8 fine bins/thread, bin-center mapping (exact minmax) ---
    float minf = __int_as_float(g_minJ[c]);
    float maxf = __int_as_float(g_maxJ[c]);
    float step = (maxf - minf) * (1.0f / NB);
    float sden = fmaxf(step, 1e-12f);
    {
        int baseJ = c * JFINE + tile * JTILE + t * 8;
        int4 ja0 = *(const int4*)&g_cntJA[baseJ];
        int4 ja1 = *(const int4*)&g_cntJA[baseJ + 4];
        int4 jb0 = *(const int4*)&g_cntJB[baseJ];
        int4 jb1 = *(const int4*)&g_cntJB[baseJ + 4];
        int jc[8] = {ja0.x + jb0.x, ja0.y + jb0.y, ja0.z + jb0.z, ja0.w + jb0.w,
                     ja1.x + jb1.x, ja1.y + jb1.y, ja1.z + jb1.z, ja1.w + jb1.w};
        int* h = shh + (t & 1) * NB;
        #pragma unroll
        for (int k = 0; k < 8; k++) {
            if (jc[k]) {
                float v = ((float)(tile * JTILE + t * 8 + k) + 0.5f) * JWBIN;
                int b = (int)floorf((v - minf) / sden);
                b = max(0, min(NB - 1, b));
                atomicAdd(&h[b], jc[k]);
            }
        }
    }

    // --- I scan: 4 bins/thread ---
    int base = c * IFINE + tile * ITILE + t * 4;
    int4 a0 = *(const int4*)&g_cntA[base];
    int4 b0 = *(const int4*)&g_cntB[base];
    int v[4] = {a0.x + b0.x, a0.y + b0.y, a0.z + b0.z, a0.w + b0.w};
    int loc[4];
    int run = 0;
    #pragma unroll
    for (int k = 0; k < 4; k++) { loc[k] = run; run += v[k]; }
    int lane = t & 31, wid = t >> 5;
    int x = run;
    for (int o = 1; o < 32; o <<= 1) {
        int u = __shfl_up_sync(0xFFFFFFFFu, x, o);
        if (lane >= o) x += u;
    }
    __shared__ int wsum[8];
    if (lane == 31) wsum[wid] = x;
    __syncthreads();
    if (t < 8) {
        int y = wsum[t];
        for (int o = 1; o < 8; o <<= 1) {
            int u = __shfl_up_sync(0xFFu, y, o);
            if (t >= o) y += u;
        }
        wsum[t] = y;
    }
    __syncthreads();
    int ex = x - run + (wid ? wsum[wid - 1] : 0);
    *(int4*)&g_cntA[base] = make_int4(ex + loc[0], ex + loc[1], ex + loc[2], ex + loc[3]);
    if (t == 255) g_tbase[c * NT + tile] = ex + run;

    // --- flush coarse histogram ---
    __syncthreads();
    int s2 = shh[t] + shh[t + NB];
    if (s2) atomicAdd(&g_histJ[c * NB + t], s2);
}

// ---------------- K3: closed-form per-bin loss ----------------------------------------
__global__ void k_loss(float* __restrict__ out) {
    int c = blockIdx.y, tile = blockIdx.x, t = threadIdx.x;   // 256 threads, 4 bins each
    __shared__ float scum[NB], shis[NB];
    __shared__ int sicum[NB];
    __shared__ int stb[NT + 1];
    int hraw = g_histJ[c * NB + t];
    if (t < NT) {
        int tot = g_tbase[c * NT + t];
        int incl = tot;
        for (int o = 1; o < NT; o <<= 1) {
            int u = __shfl_up_sync(0xFFFFu, incl, o);
            if (t >= o) incl += u;
        }
        stb[t] = incl - tot;
        if (t == NT - 1) stb[NT] = incl;                 // channel total = nI
    }
    sicum[t] = hraw;
    __syncthreads();
    for (int o = 1; o < NB; o <<= 1) {
        int add = (t >= o) ? sicum[t - o] : 0;
        __syncthreads();
        sicum[t] += add;
        __syncthreads();
    }
    float nI = (float)stb[NT];
    float nJ = (float)sicum[NB - 1];
    float scale = nI / nJ;
    scum[t] = (float)sicum[t] * scale;
    shis[t] = (float)hraw * scale;
    __syncthreads();

    float minf = __int_as_float(g_minJ[c]);
    float maxf = __int_as_float(g_maxJ[c]);
    float step = (maxf - minf) * (1.0f / NB);

    int base = c * IFINE + tile * ITILE + t * 4;
    int4 a = *(const int4*)&g_cntA[base];
    int o5[5] = {a.x, a.y, a.z, a.w, 0};
    int tb = stb[tile];
    if (t < 255) o5[4] = g_cntA[base + 4];
    int e_thread_last = (t < 255) ? (tb + o5[4]) : stb[tile + 1];

    int bi = -1;
    float cum_bi = 0.0f, lo = 0.0f, invh = 0.0f, fb = 0.0f;
    float acc = 0.0f;

    for (int k = 0; k < 4; k++) {
        int s = tb + o5[k];
        int e = (k < 3) ? (tb + o5[k + 1]) : e_thread_last;
        if (e <= s) continue;
        float xb = ((float)(tile * ITILE + t * 4 + k) + 0.5f) * IWBIN;  // bin center
        int r0 = s + 1;
        while (r0 <= e) {
            if (bi < 0) {
                float r = (float)r0;
                int pos = 0;
                #pragma unroll
                for (int st = 128; st > 0; st >>= 1) {
                    int np = pos + st;
                    if (np <= NB && scum[np - 1] < r) pos = np;
                }
                bi = pos > NB - 1 ? NB - 1 : pos;
                cum_bi = scum[bi]; float hb = shis[bi];
                lo = cum_bi - hb; invh = 1.0f / fmaxf(hb, 1e-12f);
                fb = minf + (float)bi * step;
            } else {
                while ((float)r0 > cum_bi && bi < NB - 1) {
                    bi++;
                    cum_bi = scum[bi]; float hb = shis[bi];
                    lo = cum_bi - hb; invh = 1.0f / fmaxf(hb, 1e-12f);
                    fb = minf + (float)bi * step;
                }
            }
            if (bi == NB - 1 && (float)r0 > cum_bi) {    // clamp region: ratio = 1
                float d = xb - (fb + step);
                float fn = (float)(e - r0 + 1);
                acc = fmaf(fn * d, d, acc);
                r0 = e + 1;
                continue;
            }
            int rend = e;
            if ((float)e > cum_bi) {
                int rb = (int)floorf(cum_bi);
                rend = rb < e ? rb : e;
            }
            float a0 = xb - fb - ((float)r0 - lo) * invh * step;
            float q  = -invh * step;
            float fn = (float)(rend - r0 + 1);
            float s1 = 0.5f * fn * (fn - 1.0f);
            float s2 = (fn - 1.0f) * fn * (2.0f * fn - 1.0f) * (1.0f / 6.0f);
            acc += fn * a0 * a0 + 2.0f * a0 * q * s1 + q * q * s2;
            r0 = rend + 1;
        }
    }

    double dacc = (double)acc;
    for (int o = 16; o; o >>= 1) dacc += __shfl_down_sync(0xFFFFFFFFu, dacc, o);
    __shared__ double sacc[8];
    if ((t & 31) == 0) sacc[t >> 5] = dacc;
    __syncthreads();
    if (t < 8) {
        double v = sacc[t];
        for (int o = 4; o; o >>= 1) v += __shfl_down_sync(0xFFu, v, o);
        if (t == 0) {
            atomicAdd(&g_loss, v);
            __threadfence();
            unsigned int ticket = atomicAdd(&g_done, 1u);
            if (ticket == (unsigned)(CC * NT) - 1) {
                double tot = atomicAdd(&g_loss, 0.0);
                out[0] = (float)(tot * (100.0 / ((double)CC * (double)HWN)));
            }
        }
    }
}

extern "C" void kernel_launch(void* const* d_in, const int* in_sizes, int n_in,
                              void* d_out, int out_size) {
    const float* I = (const float*)d_in[0];
    const float* J = (const float*)d_in[1];
    const int*  mI = (const int*)d_in[2];
    const int*  mJ = (const int*)d_in[3];
    float* out = (float*)d_out;

    static bool s_cfg = false;
    if (!s_cfg) {
        cudaFuncSetAttribute(k_hist, cudaFuncAttributeMaxDynamicSharedMemorySize, SMEM_HIST);
        s_cfg = true;
    }

    dim3 gs(NT, CC);                // 16 x 64

    k_init<<<(CC * NB) / 256, 256>>>();
    k_hist<<<2 * CC, 1024, SMEM_HIST>>>((const float4*)I, (const float4*)J,
                                        (const int4*)mI, (const int4*)mJ);
    k_mid<<<gs, 256>>>();
    k_loss<<<gs, 256>>>(out);
}